// round 1
// baseline (speedup 1.0000x reference)
#include <cuda_runtime.h>

#define BB 256
#define TT 256
#define CC 384
#define HS 64
#define BT (BB*TT)

// Scratch (allocation-free rule: __device__ globals)
__device__ float g_q[BT*HS];
__device__ float g_k[BT*HS];
__device__ float g_v[BT*HS];

// ---------------------------------------------------------------------------
// QKV projection: out[BT,192] = x[BT,384] @ [Wq|Wk|Wv] + bias
// CTA tile: 64 rows x 192 cols, K-tile 16. Thread tile 4x12 (256 thr = 16x16).
// ---------------------------------------------------------------------------
__global__ __launch_bounds__(256) void qkv_kernel(
    const float* __restrict__ x,
    const float* __restrict__ Wq, const float* __restrict__ bq,
    const float* __restrict__ Wk, const float* __restrict__ bk,
    const float* __restrict__ Wv, const float* __restrict__ bv)
{
    __shared__ float xs[64][20];   // [row][k], pad 20 keeps float4 stores aligned
    __shared__ float ws[16][192];  // [k][col]

    const int tid = threadIdx.x;
    const int tr  = tid >> 4;   // 0..15 (row group)
    const int tc  = tid & 15;   // 0..15 (col group)
    const int rowbase = blockIdx.x * 64;

    float acc[4][12];
    #pragma unroll
    for (int i = 0; i < 4; i++)
        #pragma unroll
        for (int j = 0; j < 12; j++) acc[i][j] = 0.f;

    const int xr = tid >> 2;         // 0..63
    const int xk = (tid & 3) << 2;   // 0,4,8,12

    for (int k0 = 0; k0 < CC; k0 += 16) {
        // stage x tile: 64x16
        float4 xv = *(const float4*)(x + (size_t)(rowbase + xr) * CC + k0 + xk);
        *(float4*)&xs[xr][xk] = xv;
        // stage W tile: 16x192 (three matrices side by side)
        #pragma unroll
        for (int p = 0; p < 3; p++) {
            int e4 = tid + 256 * p;        // 0..767
            int kk = e4 / 48;              // 0..15
            int cq = (e4 % 48) << 2;       // 0..188 step 4
            const float* W = (cq < 64) ? Wq : (cq < 128 ? Wk : Wv);
            int cc2 = cq & 63;
            *(float4*)&ws[kk][cq] = *(const float4*)(W + (size_t)(k0 + kk) * HS + cc2);
        }
        __syncthreads();

        #pragma unroll
        for (int kk = 0; kk < 16; kk++) {
            float a[4], bb[12];
            #pragma unroll
            for (int i = 0; i < 4; i++) a[i] = xs[tr + 16 * i][kk];
            #pragma unroll
            for (int j = 0; j < 12; j++) bb[j] = ws[kk][tc + 16 * j];
            #pragma unroll
            for (int i = 0; i < 4; i++)
                #pragma unroll
                for (int j = 0; j < 12; j++)
                    acc[i][j] = fmaf(a[i], bb[j], acc[i][j]);
        }
        __syncthreads();
    }

    // epilogue: add bias, scatter to q/k/v scratch
    #pragma unroll
    for (int i = 0; i < 4; i++) {
        int r = rowbase + tr + 16 * i;
        #pragma unroll
        for (int j = 0; j < 12; j++) {
            int c = tc + 16 * j;
            float val = acc[i][j];
            if (j < 4)        g_q[(size_t)r * HS + c]         = val + bq[c];
            else if (j < 8)   g_k[(size_t)r * HS + (c - 64)]  = val + bk[c - 64];
            else              g_v[(size_t)r * HS + (c - 128)] = val + bv[c - 128];
        }
    }
}

// ---------------------------------------------------------------------------
// Attention: one CTA per batch. K,V resident in smem (131 KB fp32).
// One thread per query row, online softmax, float4 broadcast smem reads.
// ---------------------------------------------------------------------------
__global__ __launch_bounds__(256) void attn_kernel(float* __restrict__ out)
{
    extern __shared__ float sm[];
    float* Ks = sm;                  // [T][HS]
    float* Vs = sm + TT * HS;        // [T][HS]

    const int b = blockIdx.x;
    const int t = threadIdx.x;

    const float4* kg = (const float4*)(g_k + (size_t)b * TT * HS);
    const float4* vg = (const float4*)(g_v + (size_t)b * TT * HS);
    for (int e = t; e < TT * HS / 4; e += 256) {
        ((float4*)Ks)[e] = kg[e];
        ((float4*)Vs)[e] = vg[e];
    }
    __syncthreads();

    float q[HS];
    const float* qg = g_q + ((size_t)b * TT + t) * HS;
    #pragma unroll
    for (int d = 0; d < HS; d++) q[d] = qg[d] * 0.125f;   // scale = HS^-0.5 = 1/8

    float m = -1e30f, l = 0.f;
    float acc[HS];
    #pragma unroll
    for (int d = 0; d < HS; d++) acc[d] = 0.f;

    for (int s = 0; s <= t; s++) {
        const float4* kp = (const float4*)(Ks + s * HS);
        float dA = 0.f, dB = 0.f, dC = 0.f, dD = 0.f;
        #pragma unroll
        for (int u = 0; u < 16; u++) {
            float4 kv = kp[u];
            dA = fmaf(q[4 * u + 0], kv.x, dA);
            dB = fmaf(q[4 * u + 1], kv.y, dB);
            dC = fmaf(q[4 * u + 2], kv.z, dC);
            dD = fmaf(q[4 * u + 3], kv.w, dD);
        }
        float dot = (dA + dB) + (dC + dD);

        float nm   = fmaxf(m, dot);
        float p    = __expf(dot - nm);
        float corr = __expf(m - nm);
        l = l * corr + p;

        const float4* vp = (const float4*)(Vs + s * HS);
        #pragma unroll
        for (int u = 0; u < 16; u++) {
            float4 vv = vp[u];
            acc[4 * u + 0] = fmaf(p, vv.x, acc[4 * u + 0] * corr);
            acc[4 * u + 1] = fmaf(p, vv.y, acc[4 * u + 1] * corr);
            acc[4 * u + 2] = fmaf(p, vv.z, acc[4 * u + 2] * corr);
            acc[4 * u + 3] = fmaf(p, vv.w, acc[4 * u + 3] * corr);
        }
        m = nm;
    }

    float inv = 1.f / l;
    float* op = out + ((size_t)b * TT + t) * HS;
    #pragma unroll
    for (int d = 0; d < HS; d++) op[d] = acc[d] * inv;
}

extern "C" void kernel_launch(void* const* d_in, const int* in_sizes, int n_in,
                              void* d_out, int out_size)
{
    const float* x  = (const float*)d_in[0];
    const float* Wq = (const float*)d_in[1];
    const float* bq = (const float*)d_in[2];
    const float* Wk = (const float*)d_in[3];
    const float* bk = (const float*)d_in[4];
    const float* Wv = (const float*)d_in[5];
    const float* bv = (const float*)d_in[6];
    float* out = (float*)d_out;

    qkv_kernel<<<BT / 64, 256>>>(x, Wq, bq, Wk, bk, Wv, bv);

    const int smem_bytes = 2 * TT * HS * (int)sizeof(float);  // 131072
    cudaFuncSetAttribute(attn_kernel, cudaFuncAttributeMaxDynamicSharedMemorySize, smem_bytes);
    attn_kernel<<<BB, 256, smem_bytes>>>(out);
}

// round 2
// speedup vs baseline: 1.0016x; 1.0016x over previous
#include <cuda_runtime.h>

#define BB 256
#define TT 256
#define CC 384
#define HS 64
#define BT (BB*TT)

// Scratch (allocation-free rule: __device__ globals)
__device__ float g_q[BT*HS];
__device__ float g_k[BT*HS];
__device__ float g_v[BT*HS];

// ---------------------------------------------------------------------------
// QKV projection: out[BT,192] = x[BT,384] @ [Wq|Wk|Wv] + bias
// CTA tile: 64 rows x 192 cols, K-tile 16. Thread tile 4x12 (256 thr = 16x16).
// ---------------------------------------------------------------------------
__global__ __launch_bounds__(256) void qkv_kernel(
    const float* __restrict__ x,
    const float* __restrict__ Wq, const float* __restrict__ bq,
    const float* __restrict__ Wk, const float* __restrict__ bk,
    const float* __restrict__ Wv, const float* __restrict__ bv)
{
    __shared__ float xs[64][20];   // [row][k], pad 20 keeps float4 stores aligned
    __shared__ float ws[16][192];  // [k][col]

    const int tid = threadIdx.x;
    const int tr  = tid >> 4;   // 0..15 (row group)
    const int tc  = tid & 15;   // 0..15 (col group)
    const int rowbase = blockIdx.x * 64;

    float acc[4][12];
    #pragma unroll
    for (int i = 0; i < 4; i++)
        #pragma unroll
        for (int j = 0; j < 12; j++) acc[i][j] = 0.f;

    const int xr = tid >> 2;         // 0..63
    const int xk = (tid & 3) << 2;   // 0,4,8,12

    for (int k0 = 0; k0 < CC; k0 += 16) {
        // stage x tile: 64x16
        float4 xv = *(const float4*)(x + (size_t)(rowbase + xr) * CC + k0 + xk);
        *(float4*)&xs[xr][xk] = xv;
        // stage W tile: 16x192 (three matrices side by side)
        #pragma unroll
        for (int p = 0; p < 3; p++) {
            int e4 = tid + 256 * p;        // 0..767
            int kk = e4 / 48;              // 0..15
            int cq = (e4 % 48) << 2;       // 0..188 step 4
            const float* W = (cq < 64) ? Wq : (cq < 128 ? Wk : Wv);
            int cc2 = cq & 63;
            *(float4*)&ws[kk][cq] = *(const float4*)(W + (size_t)(k0 + kk) * HS + cc2);
        }
        __syncthreads();

        #pragma unroll
        for (int kk = 0; kk < 16; kk++) {
            float a[4], bb[12];
            #pragma unroll
            for (int i = 0; i < 4; i++) a[i] = xs[tr + 16 * i][kk];
            #pragma unroll
            for (int j = 0; j < 12; j++) bb[j] = ws[kk][tc + 16 * j];
            #pragma unroll
            for (int i = 0; i < 4; i++)
                #pragma unroll
                for (int j = 0; j < 12; j++)
                    acc[i][j] = fmaf(a[i], bb[j], acc[i][j]);
        }
        __syncthreads();
    }

    // epilogue: add bias, scatter to q/k/v scratch
    #pragma unroll
    for (int i = 0; i < 4; i++) {
        int r = rowbase + tr + 16 * i;
        #pragma unroll
        for (int j = 0; j < 12; j++) {
            int c = tc + 16 * j;
            float val = acc[i][j];
            if (j < 4)        g_q[(size_t)r * HS + c]         = val + bq[c];
            else if (j < 8)   g_k[(size_t)r * HS + (c - 64)]  = val + bk[c - 64];
            else              g_v[(size_t)r * HS + (c - 128)] = val + bv[c - 128];
        }
    }
}

// ---------------------------------------------------------------------------
// Attention: one CTA per batch. K,V resident in smem (131 KB fp32).
// One thread per query row, online softmax, float4 broadcast smem reads.
// ---------------------------------------------------------------------------
__global__ __launch_bounds__(256) void attn_kernel(float* __restrict__ out)
{
    extern __shared__ float sm[];
    float* Ks = sm;                  // [T][HS]
    float* Vs = sm + TT * HS;        // [T][HS]

    const int b = blockIdx.x;
    const int t = threadIdx.x;

    const float4* kg = (const float4*)(g_k + (size_t)b * TT * HS);
    const float4* vg = (const float4*)(g_v + (size_t)b * TT * HS);
    for (int e = t; e < TT * HS / 4; e += 256) {
        ((float4*)Ks)[e] = kg[e];
        ((float4*)Vs)[e] = vg[e];
    }
    __syncthreads();

    float q[HS];
    const float* qg = g_q + ((size_t)b * TT + t) * HS;
    #pragma unroll
    for (int d = 0; d < HS; d++) q[d] = qg[d] * 0.125f;   // scale = HS^-0.5 = 1/8

    float m = -1e30f, l = 0.f;
    float acc[HS];
    #pragma unroll
    for (int d = 0; d < HS; d++) acc[d] = 0.f;

    for (int s = 0; s <= t; s++) {
        const float4* kp = (const float4*)(Ks + s * HS);
        float dA = 0.f, dB = 0.f, dC = 0.f, dD = 0.f;
        #pragma unroll
        for (int u = 0; u < 16; u++) {
            float4 kv = kp[u];
            dA = fmaf(q[4 * u + 0], kv.x, dA);
            dB = fmaf(q[4 * u + 1], kv.y, dB);
            dC = fmaf(q[4 * u + 2], kv.z, dC);
            dD = fmaf(q[4 * u + 3], kv.w, dD);
        }
        float dot = (dA + dB) + (dC + dD);

        float nm   = fmaxf(m, dot);
        float p    = __expf(dot - nm);
        float corr = __expf(m - nm);
        l = l * corr + p;

        const float4* vp = (const float4*)(Vs + s * HS);
        #pragma unroll
        for (int u = 0; u < 16; u++) {
            float4 vv = vp[u];
            acc[4 * u + 0] = fmaf(p, vv.x, acc[4 * u + 0] * corr);
            acc[4 * u + 1] = fmaf(p, vv.y, acc[4 * u + 1] * corr);
            acc[4 * u + 2] = fmaf(p, vv.z, acc[4 * u + 2] * corr);
            acc[4 * u + 3] = fmaf(p, vv.w, acc[4 * u + 3] * corr);
        }
        m = nm;
    }

    float inv = 1.f / l;
    float* op = out + ((size_t)b * TT + t) * HS;
    #pragma unroll
    for (int d = 0; d < HS; d++) op[d] = acc[d] * inv;
}

extern "C" void kernel_launch(void* const* d_in, const int* in_sizes, int n_in,
                              void* d_out, int out_size)
{
    const float* x  = (const float*)d_in[0];
    const float* Wq = (const float*)d_in[1];
    const float* bq = (const float*)d_in[2];
    const float* Wk = (const float*)d_in[3];
    const float* bk = (const float*)d_in[4];
    const float* Wv = (const float*)d_in[5];
    const float* bv = (const float*)d_in[6];
    float* out = (float*)d_out;

    qkv_kernel<<<BT / 64, 256>>>(x, Wq, bq, Wk, bk, Wv, bv);

    const int smem_bytes = 2 * TT * HS * (int)sizeof(float);  // 131072
    cudaFuncSetAttribute(attn_kernel, cudaFuncAttributeMaxDynamicSharedMemorySize, smem_bytes);
    attn_kernel<<<BB, 256, smem_bytes>>>(out);
}